// round 1
// baseline (speedup 1.0000x reference)
#include <cuda_runtime.h>
#include <cuda_bf16.h>

// Problem constants
#define Bn 8
#define Sn 16
#define Hn 32
#define Wn 32
#define En 128
#define NHn 8
#define HDn 16
#define TOK (Bn*Sn*Hn*Wn)      // 131072
#define Pn (Bn*Hn*Wn)          // 8192 positions per step
#define OC 512                 // 4E
#define KCONV 1152             // 9 taps * 128 ic

// -------- scratch (device globals; no allocation allowed) --------
__device__ float g_xln[TOK*En];            // 64MB
__device__ float g_xres[TOK*En];           // 64MB
__device__ float g_ccx[(long)TOK*OC];      // 256MB  cc accumulator per (s,p,oc)
__device__ float g_h[Pn*En];               // 4MB
__device__ float g_c[Pn*En];               // 4MB
__device__ float g_wx[9*128*OC];           // reordered conv weights (x half)
__device__ float g_wh[9*128*OC];           // reordered conv weights (h half)

// -------------------- zero init --------------------
__global__ void zero_kernel(float* p, int n) {
    int i = blockIdx.x*blockDim.x + threadIdx.x;
    if (i < n) p[i] = 0.f;
}

// -------------------- weight reorder --------------------
// conv_k: (512, 256, 3, 3) -> Wr[k= tap*128+ic][oc], tap = ky*3+kx
__global__ void reorder_w(const float* __restrict__ ck,
                          float* __restrict__ wx, float* __restrict__ wh) {
    int idx = blockIdx.x*blockDim.x + threadIdx.x;
    if (idx >= 9*128*OC) return;
    int oc  = idx & 511;
    int r   = idx >> 9;          // tap*128 + ic
    int tap = r >> 7, ic = r & 127;
    int ky = tap / 3, kx = tap % 3;
    wx[idx] = ck[(((long)oc*256 + ic      )*3 + ky)*3 + kx];
    wh[idx] = ck[(((long)oc*256 + 128 + ic)*3 + ky)*3 + kx];
}

// -------------------- proj + silu + LN --------------------
// block: 128 threads, 16 tokens
__global__ __launch_bounds__(128)
void projln_kernel(const float* __restrict__ inp, const float* __restrict__ Wp,
                   const float* __restrict__ gamma, const float* __restrict__ beta,
                   float* __restrict__ xln) {
    __shared__ float xs[16][128];
    __shared__ float mu_s[16], rs_s[16];
    long tok0 = (long)blockIdx.x * 16;
    int j = threadIdx.x;
    #pragma unroll
    for (int t = 0; t < 16; t++)
        xs[t][j] = inp[(tok0+t)*128 + j];
    __syncthreads();
    float acc[16];
    #pragma unroll
    for (int t=0;t<16;t++) acc[t]=0.f;
    #pragma unroll 8
    for (int k=0;k<128;k+=4) {
        float w0=Wp[(k+0)*128+j], w1=Wp[(k+1)*128+j], w2=Wp[(k+2)*128+j], w3=Wp[(k+3)*128+j];
        #pragma unroll
        for (int t=0;t<16;t++) {
            float4 xv = *(const float4*)&xs[t][k];
            acc[t] += xv.x*w0 + xv.y*w1 + xv.z*w2 + xv.w*w3;
        }
    }
    #pragma unroll
    for (int t=0;t<16;t++) {
        float v = acc[t];
        acc[t] = v / (1.0f + __expf(-v));   // silu
    }
    __syncthreads();
    #pragma unroll
    for (int t=0;t<16;t++) xs[t][j] = acc[t];
    __syncthreads();
    int warp = j >> 5, lane = j & 31;
    for (int t = warp*4; t < warp*4+4; t++) {
        float a0 = xs[t][lane], a1 = xs[t][lane+32], a2 = xs[t][lane+64], a3 = xs[t][lane+96];
        float s = a0+a1+a2+a3;
        float q = a0*a0+a1*a1+a2*a2+a3*a3;
        #pragma unroll
        for (int off=16; off; off>>=1) {
            s += __shfl_xor_sync(0xffffffff, s, off);
            q += __shfl_xor_sync(0xffffffff, q, off);
        }
        if (lane==0) {
            float mu = s * (1.0f/128.0f);
            float var = q * (1.0f/128.0f) - mu*mu;
            mu_s[t] = mu;
            rs_s[t] = rsqrtf(var + 1e-5f);
        }
    }
    __syncthreads();
    float g = gamma[j], bt = beta[j];
    #pragma unroll
    for (int t=0;t<16;t++)
        xln[(tok0+t)*128 + j] = (xs[t][j]-mu_s[t])*rs_s[t]*g + bt;
}

// -------------------- fused qkv + attention + out-proj + residual --------------------
// one block per (b, hw). 384 threads.
__global__ __launch_bounds__(384)
void attn_kernel(const float* __restrict__ xln, const float* __restrict__ W_in,
                 const float* __restrict__ W_out, const float* __restrict__ inp,
                 float* __restrict__ xres) {
    __shared__ float xs[16][128];
    __shared__ float qkv[16][384];
    __shared__ float ao[16][128];
    int bid = blockIdx.x;
    int b = bid >> 10, hw = bid & 1023;
    int tid = threadIdx.x;

    for (int t = tid; t < 16*128; t += 384) {
        int s = t >> 7, j = t & 127;
        xs[s][j] = xln[((long)(b*16+s)*1024 + hw)*128 + j];
    }
    __syncthreads();
    {   // qkv: thread j computes column j for all 16 tokens
        int j = tid;
        float acc[16];
        #pragma unroll
        for (int s=0;s<16;s++) acc[s]=0.f;
        #pragma unroll 4
        for (int k = 0; k < 128; k += 4) {
            float w0 = W_in[(k+0)*384 + j];
            float w1 = W_in[(k+1)*384 + j];
            float w2 = W_in[(k+2)*384 + j];
            float w3 = W_in[(k+3)*384 + j];
            #pragma unroll
            for (int s=0;s<16;s++) {
                float4 xv = *(const float4*)&xs[s][k];
                acc[s] += xv.x*w0 + xv.y*w1 + xv.z*w2 + xv.w*w3;
            }
        }
        #pragma unroll
        for (int s=0;s<16;s++) qkv[s][j] = acc[s];
    }
    __syncthreads();
    if (tid < 128) {   // per (head, query-row) softmax attention
        int i = tid >> 4, srow = tid & 15;
        float qd[16];
        #pragma unroll
        for (int d=0; d<16; d++) qd[d] = qkv[srow][i*48+d];
        float sc[16];
        float mx = -1e30f;
        #pragma unroll
        for (int l=0;l<16;l++) {
            float sv = 0.f;
            #pragma unroll
            for (int d=0;d<16;d++) sv += qd[d]*qkv[l][i*48+16+d];
            sv = sv*0.25f + (l<=srow ? 1.0f : -1000.0f);
            sc[l]=sv; mx = fmaxf(mx, sv);
        }
        float sum=0.f;
        #pragma unroll
        for (int l=0;l<16;l++){ sc[l]=__expf(sc[l]-mx); sum+=sc[l]; }
        float inv = 1.0f/sum;
        float o[16];
        #pragma unroll
        for (int d=0;d<16;d++) o[d]=0.f;
        #pragma unroll
        for (int l=0;l<16;l++) {
            float wl = sc[l]*inv;
            #pragma unroll
            for (int d=0;d<16;d++) o[d] += wl*qkv[l][i*48+32+d];
        }
        #pragma unroll
        for (int d=0;d<16;d++) ao[srow][i*16+d]=o[d];
    }
    __syncthreads();
    if (tid < 128) {   // out projection + residual
        int j = tid;
        float acc[16];
        #pragma unroll
        for (int s=0;s<16;s++) acc[s]=0.f;
        #pragma unroll 4
        for (int k=0;k<128;k+=4) {
            float w0 = W_out[(k+0)*128+j];
            float w1 = W_out[(k+1)*128+j];
            float w2 = W_out[(k+2)*128+j];
            float w3 = W_out[(k+3)*128+j];
            #pragma unroll
            for (int s=0;s<16;s++) {
                float4 av = *(const float4*)&ao[s][k];
                acc[s] += av.x*w0+av.y*w1+av.z*w2+av.w*w3;
            }
        }
        #pragma unroll
        for (int s=0;s<16;s++) {
            long t = ((long)(b*16+s)*1024+hw)*128 + j;
            xres[t] = acc[s] + inp[t];
        }
    }
}

// -------------------- implicit-GEMM 3x3 conv --------------------
// C[m, oc] (+)= sum over (tap, ic) of in[n, y+ky-1, x+kx-1, ic] * Wr[tap*128+ic][oc]
// M tile 128, N tile 128, K step 16. 256 threads, 8x8 per thread.
template<bool ACC>
__global__ __launch_bounds__(256, 2)
void conv_gemm(const float* __restrict__ in_base, long in_z_stride, long in_b_stride,
               const float* __restrict__ Wr,
               float* __restrict__ out_base, long out_z_stride) {
    const float* in0 = in_base + (long)blockIdx.z * in_z_stride;
    float* out = out_base + (long)blockIdx.z * out_z_stride;

    __shared__ float As[16][128];
    __shared__ float Bs[16][128];

    int tid = threadIdx.x;
    int m0 = blockIdx.x * 128;
    int n0 = blockIdx.y * 128;

    int ar  = tid >> 2;          // row 0..63 (and +64)
    int akq = (tid & 3) * 4;     // k sub-offset in chunk
    int bkr = tid >> 5;          // 0..7 (and +8)
    int bn4 = (tid & 31) * 4;

    // precompute spatial for the two A rows this thread loads
    int gr0 = m0 + ar;
    int gr1 = m0 + ar + 64;
    int b0 = gr0 >> 10, y0 = (gr0 >> 5) & 31, x0 = gr0 & 31;
    int b1 = gr1 >> 10, y1 = (gr1 >> 5) & 31, x1 = gr1 & 31;

    float acc[8][8];
    #pragma unroll
    for (int i=0;i<8;i++)
        #pragma unroll
        for (int j=0;j<8;j++) acc[i][j]=0.f;

    int ty = tid >> 4, tx = tid & 15;

    for (int k0 = 0; k0 < KCONV; k0 += 16) {
        int tap = k0 >> 7;
        int ic0 = (k0 & 127) + akq;
        int ky = tap / 3 - 1, kx = tap % 3 - 1;
        // A load (gather with halo masking)
        {
            int yy = y0 + ky, xx = x0 + kx;
            float4 v = make_float4(0.f,0.f,0.f,0.f);
            if ((unsigned)yy < 32u && (unsigned)xx < 32u)
                v = *(const float4*)(in0 + (long)b0*in_b_stride + ((yy<<5)+xx)*128 + ic0);
            As[akq+0][ar] = v.x; As[akq+1][ar] = v.y; As[akq+2][ar] = v.z; As[akq+3][ar] = v.w;
        }
        {
            int yy = y1 + ky, xx = x1 + kx;
            float4 v = make_float4(0.f,0.f,0.f,0.f);
            if ((unsigned)yy < 32u && (unsigned)xx < 32u)
                v = *(const float4*)(in0 + (long)b1*in_b_stride + ((yy<<5)+xx)*128 + ic0);
            As[akq+0][ar+64] = v.x; As[akq+1][ar+64] = v.y; As[akq+2][ar+64] = v.z; As[akq+3][ar+64] = v.w;
        }
        // B load (direct, coalesced)
        *(float4*)&Bs[bkr  ][bn4] = *(const float4*)(Wr + (long)(k0+bkr  )*OC + n0 + bn4);
        *(float4*)&Bs[bkr+8][bn4] = *(const float4*)(Wr + (long)(k0+bkr+8)*OC + n0 + bn4);
        __syncthreads();
        #pragma unroll
        for (int kk = 0; kk < 16; kk++) {
            float4 a0 = *(const float4*)&As[kk][ty*8];
            float4 a1 = *(const float4*)&As[kk][ty*8+4];
            float4 bq0 = *(const float4*)&Bs[kk][tx*8];
            float4 bq1 = *(const float4*)&Bs[kk][tx*8+4];
            float fa[8] = {a0.x,a0.y,a0.z,a0.w,a1.x,a1.y,a1.z,a1.w};
            float fb[8] = {bq0.x,bq0.y,bq0.z,bq0.w,bq1.x,bq1.y,bq1.z,bq1.w};
            #pragma unroll
            for (int i=0;i<8;i++)
                #pragma unroll
                for (int j=0;j<8;j++)
                    acc[i][j] += fa[i]*fb[j];
        }
        __syncthreads();
    }
    #pragma unroll
    for (int i=0;i<8;i++) {
        int gr = m0 + ty*8 + i;
        float* orow = out + (long)gr*OC + n0 + tx*8;
        #pragma unroll
        for (int j=0;j<8;j++) {
            float v = acc[i][j];
            if (ACC) v += orow[j];
            orow[j] = v;
        }
    }
}

// -------------------- LSTM gates + output write --------------------
__global__ void gates_kernel(const float* __restrict__ cc,
                             float* __restrict__ cbuf, float* __restrict__ hbuf,
                             float* __restrict__ out, int s) {
    int idx = blockIdx.x*blockDim.x + threadIdx.x;
    if (idx >= Pn*En) return;
    int p = idx >> 7, e = idx & 127;
    const float* row = cc + (long)p*OC;
    float ci = row[e], cf = row[128+e], co = row[256+e], cg = row[384+e];
    float si = 1.f/(1.f+__expf(-ci));
    float sf = 1.f/(1.f+__expf(-cf));
    float so = 1.f/(1.f+__expf(-co));
    float c_prev = cbuf[idx];
    float c_next = sf*c_prev + si*tanhf(cg);
    float h_next = so*tanhf(c_next);
    cbuf[idx] = c_next;
    hbuf[idx] = h_next;
    int b = p >> 10, pix = p & 1023;
    out[((long)(b*16+s)*1024 + pix)*128 + e] = h_next;
}

// -------------------- launch --------------------
extern "C" void kernel_launch(void* const* d_in, const int* in_sizes, int n_in,
                              void* d_out, int out_size) {
    const float* inputs  = (const float*)d_in[0];
    const float* W_proj  = (const float*)d_in[1];
    const float* ln_g    = (const float*)d_in[2];
    const float* ln_b    = (const float*)d_in[3];
    const float* W_in    = (const float*)d_in[4];
    const float* W_out   = (const float*)d_in[5];
    const float* conv_k  = (const float*)d_in[6];
    float* out = (float*)d_out;

    float *xln, *xres, *ccx, *hb, *cb, *wx, *wh;
    cudaGetSymbolAddress((void**)&xln,  g_xln);
    cudaGetSymbolAddress((void**)&xres, g_xres);
    cudaGetSymbolAddress((void**)&ccx,  g_ccx);
    cudaGetSymbolAddress((void**)&hb,   g_h);
    cudaGetSymbolAddress((void**)&cb,   g_c);
    cudaGetSymbolAddress((void**)&wx,   g_wx);
    cudaGetSymbolAddress((void**)&wh,   g_wh);

    // reset recurrent state (graph replays must be deterministic)
    zero_kernel<<<(Pn*En+255)/256, 256>>>(cb, Pn*En);

    reorder_w<<<(9*128*OC+255)/256, 256>>>(conv_k, wx, wh);

    projln_kernel<<<TOK/16, 128>>>(inputs, W_proj, ln_g, ln_b, xln);

    attn_kernel<<<Bn*Hn*Wn, 384>>>(xln, W_in, W_out, inputs, xres);

    // batch-parallel conv_x over all 16 steps: ccx[s] = conv_x(x_res[:,s])
    conv_gemm<false><<<dim3(Pn/128, OC/128, Sn), 256>>>(
        xres, (long)1024*128, (long)Sn*1024*128, wx, ccx, (long)Pn*OC);

    // sequential ConvLSTM: cc[s] = ccx[s] + conv_h(h_{s-1}); gates
    for (int s = 0; s < Sn; s++) {
        if (s > 0) {
            conv_gemm<true><<<dim3(Pn/128, OC/128, 1), 256>>>(
                hb, 0L, (long)1024*128, wh, ccx + (long)s*Pn*OC, 0L);
        }
        gates_kernel<<<(Pn*En+255)/256, 256>>>(ccx + (long)s*Pn*OC, cb, hb, out, s);
    }
}

// round 3
// speedup vs baseline: 1.3117x; 1.3117x over previous
#include <cuda_runtime.h>
#include <cuda_bf16.h>
#include <cstdint>

// Problem constants
#define Bn 8
#define Sn 16
#define Hn 32
#define Wn 32
#define En 128
#define TOK (Bn*Sn*Hn*Wn)      // 131072
#define Pn (Bn*Hn*Wn)          // 8192 positions per step
#define OC 512                 // 4E
#define KP 3456                // 9 taps * 128 ic * 3 variants
#define NCHUNK 54              // 3456 / 64

// -------- scratch (device globals; no allocation allowed) --------
__device__ float g_xln[TOK*En];                        // 64MB
__device__ float g_ccx[(long)TOK*OC];                  // 256MB
__device__ float g_c[Pn*En];                           // 4MB
__device__ __nv_bfloat16 g_xp[(long)TOK*384];          // 100MB: split A' for conv_x
__device__ __nv_bfloat16 g_hp[(long)Pn*384];           // 6MB:   split A' for conv_h
__device__ __nv_bfloat16 g_bx[(long)OC*KP];            // 3.5MB: split B' (x half)
__device__ __nv_bfloat16 g_bh[(long)OC*KP];            // 3.5MB: split B' (h half)

// ==================== helpers ====================
__device__ __forceinline__ uint32_t smem_u32(const void* p) {
    uint32_t a;
    asm("{ .reg .u64 t; cvta.to.shared.u64 t, %1; cvt.u32.u64 %0, t; }" : "=r"(a) : "l"(p));
    return a;
}
__device__ __forceinline__ void cp16(uint32_t dst, const void* src, bool pred) {
    asm volatile("cp.async.cg.shared.global [%0], [%1], 16, %2;"
        :: "r"(dst), "l"(src), "r"(pred ? 16u : 0u));
}
#define CP_COMMIT() asm volatile("cp.async.commit_group;" ::: "memory")
#define CP_WAIT3()  asm volatile("cp.async.wait_group 3;" ::: "memory")

__device__ __forceinline__ void ldm_x4(uint32_t* r, uint32_t addr) {
    asm volatile("ldmatrix.sync.aligned.m8n8.x4.shared.b16 {%0,%1,%2,%3}, [%4];"
        : "=r"(r[0]), "=r"(r[1]), "=r"(r[2]), "=r"(r[3]) : "r"(addr));
}
__device__ __forceinline__ void mma16816(float* d, const uint32_t* a, uint32_t b0, uint32_t b1) {
    asm volatile("mma.sync.aligned.m16n8k16.row.col.f32.bf16.bf16.f32 "
        "{%0,%1,%2,%3}, {%4,%5,%6,%7}, {%8,%9}, {%0,%1,%2,%3};"
        : "+f"(d[0]), "+f"(d[1]), "+f"(d[2]), "+f"(d[3])
        : "r"(a[0]), "r"(a[1]), "r"(a[2]), "r"(a[3]), "r"(b0), "r"(b1));
}
__device__ __forceinline__ void split_bf16(float x, __nv_bfloat16& hi, __nv_bfloat16& lo) {
    hi = __float2bfloat16(x);
    lo = __float2bfloat16(x - __bfloat162float(hi));
}

// -------------------- zero init --------------------
__global__ void zero_kernel(float* p, int n) {
    int i = blockIdx.x*blockDim.x + threadIdx.x;
    if (i < n) p[i] = 0.f;
}

// -------------------- weight reorder + split --------------------
// conv_k: (512, 256, 3, 3) -> B'[oc][k'], k' = tap*384 + v*128 + ic
// v0 = hi, v1 = lo, v2 = hi  (pairs with A': v0=hi, v1=hi, v2=lo)
__global__ void reorder_w(const float* __restrict__ ck,
                          __nv_bfloat16* __restrict__ bx, __nv_bfloat16* __restrict__ bh) {
    long idx = (long)blockIdx.x*blockDim.x + threadIdx.x;
    if (idx >= (long)OC*KP) return;
    int oc = idx / KP, k = idx % KP;
    int tap = k / 384, r = k % 384;
    int v = r >> 7, ic = r & 127;
    int ky = tap / 3, kx = tap % 3;
    float wx = ck[(((long)oc*256 + ic      )*3 + ky)*3 + kx];
    float wh = ck[(((long)oc*256 + 128 + ic)*3 + ky)*3 + kx];
    __nv_bfloat16 h0, l0, h1, l1;
    split_bf16(wx, h0, l0);
    split_bf16(wh, h1, l1);
    bx[idx] = (v == 1) ? l0 : h0;
    bh[idx] = (v == 1) ? l1 : h1;
}

// -------------------- proj + silu + LN --------------------
__global__ __launch_bounds__(128)
void projln_kernel(const float* __restrict__ inp, const float* __restrict__ Wp,
                   const float* __restrict__ gamma, const float* __restrict__ beta,
                   float* __restrict__ xln) {
    __shared__ float xs[16][128];
    __shared__ float mu_s[16], rs_s[16];
    long tok0 = (long)blockIdx.x * 16;
    int j = threadIdx.x;
    #pragma unroll
    for (int t = 0; t < 16; t++)
        xs[t][j] = inp[(tok0+t)*128 + j];
    __syncthreads();
    float acc[16];
    #pragma unroll
    for (int t=0;t<16;t++) acc[t]=0.f;
    #pragma unroll 8
    for (int k=0;k<128;k+=4) {
        float w0=Wp[(k+0)*128+j], w1=Wp[(k+1)*128+j], w2=Wp[(k+2)*128+j], w3=Wp[(k+3)*128+j];
        #pragma unroll
        for (int t=0;t<16;t++) {
            float4 xv = *(const float4*)&xs[t][k];
            acc[t] += xv.x*w0 + xv.y*w1 + xv.z*w2 + xv.w*w3;
        }
    }
    #pragma unroll
    for (int t=0;t<16;t++) {
        float v = acc[t];
        acc[t] = v / (1.0f + __expf(-v));
    }
    __syncthreads();
    #pragma unroll
    for (int t=0;t<16;t++) xs[t][j] = acc[t];
    __syncthreads();
    int warp = j >> 5, lane = j & 31;
    for (int t = warp*4; t < warp*4+4; t++) {
        float a0 = xs[t][lane], a1 = xs[t][lane+32], a2 = xs[t][lane+64], a3 = xs[t][lane+96];
        float s = a0+a1+a2+a3;
        float q = a0*a0+a1*a1+a2*a2+a3*a3;
        #pragma unroll
        for (int off=16; off; off>>=1) {
            s += __shfl_xor_sync(0xffffffff, s, off);
            q += __shfl_xor_sync(0xffffffff, q, off);
        }
        if (lane==0) {
            float mu = s * (1.0f/128.0f);
            float var = q * (1.0f/128.0f) - mu*mu;
            mu_s[t] = mu;
            rs_s[t] = rsqrtf(var + 1e-5f);
        }
    }
    __syncthreads();
    float g = gamma[j], bt = beta[j];
    #pragma unroll
    for (int t=0;t<16;t++)
        xln[(tok0+t)*128 + j] = (xs[t][j]-mu_s[t])*rs_s[t]*g + bt;
}

// -------------------- qkv + attention + out-proj + residual -> split bf16 A' --------------------
__global__ __launch_bounds__(384)
void attn_kernel(const float* __restrict__ xln, const float* __restrict__ W_in,
                 const float* __restrict__ W_out, const float* __restrict__ inp,
                 __nv_bfloat16* __restrict__ xp) {
    __shared__ float xs[16][128];
    __shared__ float qkv[16][384];
    __shared__ float ao[16][128];
    int bid = blockIdx.x;
    int b = bid >> 10, hw = bid & 1023;
    int tid = threadIdx.x;

    for (int t = tid; t < 16*128; t += 384) {
        int s = t >> 7, j = t & 127;
        xs[s][j] = xln[((long)(b*16+s)*1024 + hw)*128 + j];
    }
    __syncthreads();
    {
        int j = tid;
        float acc[16];
        #pragma unroll
        for (int s=0;s<16;s++) acc[s]=0.f;
        #pragma unroll 4
        for (int k = 0; k < 128; k += 4) {
            float w0 = W_in[(k+0)*384 + j];
            float w1 = W_in[(k+1)*384 + j];
            float w2 = W_in[(k+2)*384 + j];
            float w3 = W_in[(k+3)*384 + j];
            #pragma unroll
            for (int s=0;s<16;s++) {
                float4 xv = *(const float4*)&xs[s][k];
                acc[s] += xv.x*w0 + xv.y*w1 + xv.z*w2 + xv.w*w3;
            }
        }
        #pragma unroll
        for (int s=0;s<16;s++) qkv[s][j] = acc[s];
    }
    __syncthreads();
    if (tid < 128) {
        int i = tid >> 4, srow = tid & 15;
        float qd[16];
        #pragma unroll
        for (int d=0; d<16; d++) qd[d] = qkv[srow][i*48+d];
        float sc[16];
        float mx = -1e30f;
        #pragma unroll
        for (int l=0;l<16;l++) {
            float sv = 0.f;
            #pragma unroll
            for (int d=0;d<16;d++) sv += qd[d]*qkv[l][i*48+16+d];
            sv = sv*0.25f + (l<=srow ? 1.0f : -1000.0f);
            sc[l]=sv; mx = fmaxf(mx, sv);
        }
        float sum=0.f;
        #pragma unroll
        for (int l=0;l<16;l++){ sc[l]=__expf(sc[l]-mx); sum+=sc[l]; }
        float inv = 1.0f/sum;
        float o[16];
        #pragma unroll
        for (int d=0;d<16;d++) o[d]=0.f;
        #pragma unroll
        for (int l=0;l<16;l++) {
            float wl = sc[l]*inv;
            #pragma unroll
            for (int d=0;d<16;d++) o[d] += wl*qkv[l][i*48+32+d];
        }
        #pragma unroll
        for (int d=0;d<16;d++) ao[srow][i*16+d]=o[d];
    }
    __syncthreads();
    if (tid < 128) {
        int j = tid;
        float acc[16];
        #pragma unroll
        for (int s=0;s<16;s++) acc[s]=0.f;
        #pragma unroll 4
        for (int k=0;k<128;k+=4) {
            float w0 = W_out[(k+0)*128+j];
            float w1 = W_out[(k+1)*128+j];
            float w2 = W_out[(k+2)*128+j];
            float w3 = W_out[(k+3)*128+j];
            #pragma unroll
            for (int s=0;s<16;s++) {
                float4 av = *(const float4*)&ao[s][k];
                acc[s] += av.x*w0+av.y*w1+av.z*w2+av.w*w3;
            }
        }
        #pragma unroll
        for (int s=0;s<16;s++) {
            long t = ((long)(b*16+s)*1024+hw);
            float xv = acc[s] + inp[t*128 + j];
            __nv_bfloat16 hi, lo;
            split_bf16(xv, hi, lo);
            __nv_bfloat16* xr = xp + t*384;
            xr[j]       = hi;   // v0
            xr[128 + j] = hi;   // v1
            xr[256 + j] = lo;   // v2
        }
    }
}

// -------------------- warp-MMA bf16 implicit-GEMM conv --------------------
// C tile 128x128 per CTA. 8 warps of 64x32. K'=3456 in 54 chunks of 64.
// 4-stage cp.async pipeline; ldmatrix fragment loads (144B row stride, conflict-free).
#define ROWB 144
#define STAGE_A (128*ROWB)       // 18432
#define STAGE   (2*STAGE_A)      // 36864 per stage (A + B)
#define NSTAGE  4
#define CONV_SMEM (NSTAGE*STAGE) // 147456

template<bool ACC>
__global__ __launch_bounds__(256, 1)
void conv_mma(const __nv_bfloat16* __restrict__ Ax, const __nv_bfloat16* __restrict__ Bw,
              float* __restrict__ Out, long a_bstride, long a_zstride, long o_zstride) {
    extern __shared__ char smem[];
    uint32_t sb = smem_u32(smem);

    int tid = threadIdx.x;
    int m0 = blockIdx.x * 128;
    int n0 = blockIdx.y * 128;
    int z  = blockIdx.z;

    // ---- loader geometry: thread handles row (tid>>1), segs (tid&1)*4 .. +3
    int lrow  = tid >> 1;
    int lseg0 = (tid & 1) * 4;
    int p  = m0 + lrow;
    int bb = p >> 10, y = (p >> 5) & 31, x = p & 31;
    long arow_base = (long)bb * a_bstride + (long)z * a_zstride;

    auto load_chunk = [&](int c, int st) {
        int tap  = c / 6;
        int koff = (c - tap*6) * 64;
        int ky = tap/3 - 1, kx = tap%3 - 1;
        int yy = y + ky, xx = x + kx;
        bool v = ((unsigned)yy < 32u) && ((unsigned)xx < 32u);
        const __nv_bfloat16* asrc = Ax + (arow_base + ((yy<<5) + xx)) * 384 + koff;
        if (!v) asrc = Ax;
        uint32_t abase = sb + st*STAGE + lrow*ROWB;
        const __nv_bfloat16* bsrc = Bw + (long)(n0 + lrow)*KP + c*64;
        uint32_t bbase = sb + st*STAGE + STAGE_A + lrow*ROWB;
        #pragma unroll
        for (int i = 0; i < 4; i++) {
            int seg = lseg0 + i;
            cp16(abase + seg*16, asrc + seg*8, v);
            cp16(bbase + seg*16, bsrc + seg*8, true);
        }
        CP_COMMIT();
    };

    // ---- MMA geometry
    int w = tid >> 5, l = tid & 31;
    int m_off = (w >> 2) * 64;     // 0 or 64
    int n_off = (w & 3) * 32;      // 0,32,64,96
    int lr = l & 15, lh = (l >> 4) << 4;  // ldmatrix row-lane, k-halve byte off

    float acc[4][4][4];
    #pragma unroll
    for (int i=0;i<4;i++)
        #pragma unroll
        for (int j=0;j<4;j++)
            #pragma unroll
            for (int q=0;q<4;q++) acc[i][j][q]=0.f;

    load_chunk(0, 0);
    load_chunk(1, 1);
    load_chunk(2, 2);

    for (int c = 0; c < NCHUNK; c++) {
        int st = c & (NSTAGE-1);
        if (c + 3 < NCHUNK) load_chunk(c + 3, (c + 3) & (NSTAGE-1));
        else CP_COMMIT();
        CP_WAIT3();
        __syncthreads();

        uint32_t a_st = sb + st*STAGE;
        uint32_t b_st = a_st + STAGE_A;
        #pragma unroll
        for (int ks = 0; ks < 4; ks++) {
            uint32_t af[4][4];
            #pragma unroll
            for (int mt = 0; mt < 4; mt++)
                ldm_x4(af[mt], a_st + (m_off + mt*16 + lr)*ROWB + ks*32 + lh);
            uint32_t bf[2][4];
            #pragma unroll
            for (int nt = 0; nt < 2; nt++)
                ldm_x4(bf[nt], b_st + (n_off + nt*16 + lr)*ROWB + ks*32 + lh);
            #pragma unroll
            for (int mt = 0; mt < 4; mt++) {
                #pragma unroll
                for (int n8 = 0; n8 < 4; n8++) {
                    int nt = n8 >> 1, hi = n8 & 1;
                    mma16816(acc[mt][n8], af[mt], bf[nt][hi], bf[nt][2+hi]);
                }
            }
        }
        __syncthreads();
    }

    // ---- epilogue
    #pragma unroll
    for (int mt = 0; mt < 4; mt++) {
        int r0 = m0 + m_off + mt*16 + (l >> 2);
        #pragma unroll
        for (int n8 = 0; n8 < 4; n8++) {
            int cc = n0 + n_off + n8*8 + (l & 3)*2;
            float* p0 = Out + ((long)z*o_zstride + r0    )*OC + cc;
            float* p1 = Out + ((long)z*o_zstride + r0 + 8)*OC + cc;
            float d0 = acc[mt][n8][0], d1 = acc[mt][n8][1];
            float d2 = acc[mt][n8][2], d3 = acc[mt][n8][3];
            if (ACC) { d0 += p0[0]; d1 += p0[1]; d2 += p1[0]; d3 += p1[1]; }
            p0[0] = d0; p0[1] = d1;
            p1[0] = d2; p1[1] = d3;
        }
    }
}

// -------------------- LSTM gates + output + h split --------------------
__global__ void gates_kernel(const float* __restrict__ cc,
                             float* __restrict__ cbuf,
                             __nv_bfloat16* __restrict__ hp,
                             float* __restrict__ out, int s) {
    int idx = blockIdx.x*blockDim.x + threadIdx.x;
    if (idx >= Pn*En) return;
    int p = idx >> 7, e = idx & 127;
    const float* row = cc + (long)p*OC;
    float ci = row[e], cf = row[128+e], co = row[256+e], cg = row[384+e];
    float si = 1.f/(1.f+__expf(-ci));
    float sf = 1.f/(1.f+__expf(-cf));
    float so = 1.f/(1.f+__expf(-co));
    float c_prev = cbuf[idx];
    float c_next = sf*c_prev + si*tanhf(cg);
    float h_next = so*tanhf(c_next);
    cbuf[idx] = c_next;
    __nv_bfloat16 hi, lo;
    split_bf16(h_next, hi, lo);
    __nv_bfloat16* hr = hp + (long)p*384;
    hr[e]       = hi;
    hr[128 + e] = hi;
    hr[256 + e] = lo;
    int b = p >> 10, pix = p & 1023;
    out[((long)(b*16+s)*1024 + pix)*128 + e] = h_next;
}

// -------------------- launch --------------------
extern "C" void kernel_launch(void* const* d_in, const int* in_sizes, int n_in,
                              void* d_out, int out_size) {
    const float* inputs  = (const float*)d_in[0];
    const float* W_proj  = (const float*)d_in[1];
    const float* ln_g    = (const float*)d_in[2];
    const float* ln_b    = (const float*)d_in[3];
    const float* W_in    = (const float*)d_in[4];
    const float* W_out   = (const float*)d_in[5];
    const float* conv_k  = (const float*)d_in[6];
    float* out = (float*)d_out;

    float *xln, *ccx, *cb;
    __nv_bfloat16 *xp, *hp, *bx, *bh;
    cudaGetSymbolAddress((void**)&xln, g_xln);
    cudaGetSymbolAddress((void**)&ccx, g_ccx);
    cudaGetSymbolAddress((void**)&cb,  g_c);
    cudaGetSymbolAddress((void**)&xp,  g_xp);
    cudaGetSymbolAddress((void**)&hp,  g_hp);
    cudaGetSymbolAddress((void**)&bx,  g_bx);
    cudaGetSymbolAddress((void**)&bh,  g_bh);

    cudaFuncSetAttribute(conv_mma<false>, cudaFuncAttributeMaxDynamicSharedMemorySize, CONV_SMEM);
    cudaFuncSetAttribute(conv_mma<true>,  cudaFuncAttributeMaxDynamicSharedMemorySize, CONV_SMEM);

    // reset recurrent state
    zero_kernel<<<(Pn*En+255)/256, 256>>>(cb, Pn*En);

    reorder_w<<<(int)(((long)OC*KP + 255)/256), 256>>>(conv_k, bx, bh);

    projln_kernel<<<TOK/16, 128>>>(inputs, W_proj, ln_g, ln_b, xln);

    attn_kernel<<<Bn*Hn*Wn, 384>>>(xln, W_in, W_out, inputs, xp);

    // batch-parallel conv_x over all 16 steps (A row = b*16384 + s*1024 + pix)
    conv_mma<false><<<dim3(Pn/128, OC/128, Sn), 256, CONV_SMEM>>>(
        xp, bx, ccx, /*a_bstride=*/16384L, /*a_zstride=*/1024L, /*o_zstride=*/8192L);

    // sequential ConvLSTM
    for (int s = 0; s < Sn; s++) {
        if (s > 0) {
            conv_mma<true><<<dim3(Pn/128, OC/128, 1), 256, CONV_SMEM>>>(
                hp, bh, ccx + (long)s*Pn*OC, /*a_bstride=*/1024L, 0L, 0L);
        }
        gates_kernel<<<(Pn*En+255)/256, 256>>>(ccx + (long)s*Pn*OC, cb, hp, out, s);
    }
}

// round 4
// speedup vs baseline: 2.3125x; 1.7630x over previous
#include <cuda_runtime.h>
#include <cuda_fp16.h>
#include <cstdint>

// Problem constants
#define Bn 8
#define Sn 16
#define En 128
#define TOK (Bn*Sn*32*32)      // 131072
#define Pn (Bn*32*32)          // 8192
#define OC 512
#define KROW 256               // fp16 2-term: [hi|lo] per tap

// -------- scratch (device globals) --------
__device__ float g_qkv[(long)TOK*384];        // 192MB
__device__ float g_ccx[(long)TOK*OC];         // 256MB
__device__ float g_c[Pn*En];
__device__ __half g_xs2[(long)TOK*256];       // LN out split
__device__ __half g_ao[(long)TOK*256];        // attn out split
__device__ __half g_xp[(long)TOK*256];        // residual out split (conv_x A)
__device__ __half g_hp[Pn*256];               // h split (conv_h A)
__device__ __half g_bx[(long)OC*9*256];       // conv weights x-half
__device__ __half g_bh[(long)OC*9*256];       // conv weights h-half
__device__ __half g_bqkv[384*256];
__device__ __half g_bout[128*256];

// ==================== helpers ====================
__device__ __forceinline__ uint32_t smem_u32(const void* p) {
    uint32_t a;
    asm("{ .reg .u64 t; cvta.to.shared.u64 t, %1; cvt.u32.u64 %0, t; }" : "=r"(a) : "l"(p));
    return a;
}
__device__ __forceinline__ void cp16(uint32_t dst, const void* src, bool pred) {
    asm volatile("cp.async.cg.shared.global [%0], [%1], 16, %2;"
        :: "r"(dst), "l"(src), "r"(pred ? 16u : 0u));
}
#define CP_COMMIT() asm volatile("cp.async.commit_group;" ::: "memory")
#define CP_WAIT3()  asm volatile("cp.async.wait_group 3;" ::: "memory")

__device__ __forceinline__ void ldm_x4(uint32_t* r, uint32_t addr) {
    asm volatile("ldmatrix.sync.aligned.m8n8.x4.shared.b16 {%0,%1,%2,%3}, [%4];"
        : "=r"(r[0]), "=r"(r[1]), "=r"(r[2]), "=r"(r[3]) : "r"(addr));
}
__device__ __forceinline__ void mma16816(float* d, const uint32_t* a, uint32_t b0, uint32_t b1) {
    asm volatile("mma.sync.aligned.m16n8k16.row.col.f32.f16.f16.f32 "
        "{%0,%1,%2,%3}, {%4,%5,%6,%7}, {%8,%9}, {%0,%1,%2,%3};"
        : "+f"(d[0]), "+f"(d[1]), "+f"(d[2]), "+f"(d[3])
        : "r"(a[0]), "r"(a[1]), "r"(a[2]), "r"(a[3]), "r"(b0), "r"(b1));
}
__device__ __forceinline__ void split_h(float x, __half& hi, __half& lo) {
    hi = __float2half(x);
    lo = __float2half(x - __half2float(hi));
}

// -------------------- zero init --------------------
__global__ void zero_kernel(float* p, int n) {
    int i = blockIdx.x*blockDim.x + threadIdx.x;
    if (i < n) p[i] = 0.f;
}

// -------------------- weight reorders --------------------
__global__ void reorder_conv(const float* __restrict__ ck,
                             __half* __restrict__ bx, __half* __restrict__ bh) {
    long idx = (long)blockIdx.x*blockDim.x + threadIdx.x;
    if (idx >= (long)OC*9*256) return;
    int oc = idx / (9*256), k = idx % (9*256);
    int tap = k >> 8, ic = k & 127;         // both halves identical (B = [Wh|Wh])
    int ky = tap / 3, kx = tap % 3;
    bx[idx] = __float2half(ck[(((long)oc*256 + ic      )*3 + ky)*3 + kx]);
    bh[idx] = __float2half(ck[(((long)oc*256 + 128 + ic)*3 + ky)*3 + kx]);
}
__global__ void reorder_win(const float* __restrict__ w, __half* __restrict__ b) {
    int idx = blockIdx.x*blockDim.x + threadIdx.x;
    if (idx >= 384*256) return;
    int n = idx >> 8, k = idx & 127;
    b[idx] = __float2half(w[k*384 + n]);
}
__global__ void reorder_wout(const float* __restrict__ w, __half* __restrict__ b) {
    int idx = blockIdx.x*blockDim.x + threadIdx.x;
    if (idx >= 128*256) return;
    int n = idx >> 8, k = idx & 127;
    b[idx] = __float2half(w[k*128 + n]);
}

// -------------------- proj + silu + LN -> split fp16 --------------------
__global__ __launch_bounds__(128)
void projln_kernel(const float* __restrict__ inp, const float* __restrict__ Wp,
                   const float* __restrict__ gamma, const float* __restrict__ beta,
                   __half* __restrict__ xs2) {
    __shared__ float xs[16][128];
    __shared__ float mu_s[16], rs_s[16];
    long tok0 = (long)blockIdx.x * 16;
    int j = threadIdx.x;
    #pragma unroll
    for (int t = 0; t < 16; t++)
        xs[t][j] = inp[(tok0+t)*128 + j];
    __syncthreads();
    float acc[16];
    #pragma unroll
    for (int t=0;t<16;t++) acc[t]=0.f;
    #pragma unroll 8
    for (int k=0;k<128;k+=4) {
        float w0=Wp[(k+0)*128+j], w1=Wp[(k+1)*128+j], w2=Wp[(k+2)*128+j], w3=Wp[(k+3)*128+j];
        #pragma unroll
        for (int t=0;t<16;t++) {
            float4 xv = *(const float4*)&xs[t][k];
            acc[t] += xv.x*w0 + xv.y*w1 + xv.z*w2 + xv.w*w3;
        }
    }
    #pragma unroll
    for (int t=0;t<16;t++) {
        float v = acc[t];
        acc[t] = v / (1.0f + __expf(-v));
    }
    __syncthreads();
    #pragma unroll
    for (int t=0;t<16;t++) xs[t][j] = acc[t];
    __syncthreads();
    int warp = j >> 5, lane = j & 31;
    for (int t = warp*4; t < warp*4+4; t++) {
        float a0 = xs[t][lane], a1 = xs[t][lane+32], a2 = xs[t][lane+64], a3 = xs[t][lane+96];
        float s = a0+a1+a2+a3;
        float q = a0*a0+a1*a1+a2*a2+a3*a3;
        #pragma unroll
        for (int off=16; off; off>>=1) {
            s += __shfl_xor_sync(0xffffffff, s, off);
            q += __shfl_xor_sync(0xffffffff, q, off);
        }
        if (lane==0) {
            float mu = s * (1.0f/128.0f);
            float var = q * (1.0f/128.0f) - mu*mu;
            mu_s[t] = mu;
            rs_s[t] = rsqrtf(var + 1e-5f);
        }
    }
    __syncthreads();
    float g = gamma[j], bt = beta[j];
    #pragma unroll
    for (int t=0;t<16;t++) {
        float v = (xs[t][j]-mu_s[t])*rs_s[t]*g + bt;
        __half hi, lo;
        split_h(v, hi, lo);
        xs2[(tok0+t)*256 + j]       = hi;
        xs2[(tok0+t)*256 + 128 + j] = lo;
    }
}

// -------------------- attention core (softmax + AV) --------------------
__global__ __launch_bounds__(128)
void attn_core(const float* __restrict__ qkv, __half* __restrict__ ao) {
    __shared__ float qs[16][384];
    int bid = blockIdx.x;
    int b = bid >> 10, hw = bid & 1023;
    int tid = threadIdx.x;
    for (int idx = tid; idx < 16*96; idx += 128) {
        int t = idx / 96, f = idx % 96;
        ((float4*)qs[t])[f] =
            ((const float4*)(qkv + ((long)(b*16+t)*1024 + hw)*384))[f];
    }
    __syncthreads();
    int i = tid >> 4, srow = tid & 15;
    float qd[16];
    #pragma unroll
    for (int d=0; d<16; d++) qd[d] = qs[srow][i*48+d];
    float sc[16];
    float mx = -1e30f;
    #pragma unroll
    for (int l=0;l<16;l++) {
        float sv = 0.f;
        #pragma unroll
        for (int d=0;d<16;d++) sv += qd[d]*qs[l][i*48+16+d];
        sv = sv*0.25f + (l<=srow ? 1.0f : -1000.0f);
        sc[l]=sv; mx = fmaxf(mx, sv);
    }
    float sum=0.f;
    #pragma unroll
    for (int l=0;l<16;l++){ sc[l]=__expf(sc[l]-mx); sum+=sc[l]; }
    float inv = 1.0f/sum;
    float o[16];
    #pragma unroll
    for (int d=0;d<16;d++) o[d]=0.f;
    #pragma unroll
    for (int l=0;l<16;l++) {
        float wl = sc[l]*inv;
        #pragma unroll
        for (int d=0;d<16;d++) o[d] += wl*qs[l][i*48+32+d];
    }
    long t = (long)(b*16+srow)*1024 + hw;
    #pragma unroll
    for (int d=0;d<16;d++) {
        __half hi, lo;
        split_h(o[d], hi, lo);
        ao[t*256 + i*16 + d]       = hi;
        ao[t*256 + 128 + i*16 + d] = lo;
    }
}

// -------------------- universal warp-MMA fp16 GEMM / implicit conv --------------------
// CTA tile 128x128, 16 warps of 32x32, chunks of 64 k-elems, 4-stage cp.async.
// NTAP=1: dense GEMM (K'=256).  NTAP=9: 3x3 conv gather (K'=2304).
// EPI: 0 = store f32, 1 = accumulate f32, 2 = +residual, split fp16 -> outh.
#define ROWB 144
#define STAGE_A (128*ROWB)
#define STAGE   (2*STAGE_A)       // 36864
#define NSTAGE  4
#define GEMM_SMEM (NSTAGE*STAGE)  // 147456

template<int NTAP, int EPI>
__global__ __launch_bounds__(512, 1)
void gemm_mma(const __half* __restrict__ A, const __half* __restrict__ Bw,
              float* __restrict__ Out, int ldo,
              const float* __restrict__ aux, __half* __restrict__ outh,
              long a_bstride, long a_zstride, long o_zstride) {
    constexpr int NCHUNK = NTAP * 4;
    extern __shared__ char smem[];
    uint32_t sb = smem_u32(smem);

    int tid = threadIdx.x;
    int m0 = blockIdx.x * 128;
    int n0 = blockIdx.y * 128;
    int z  = blockIdx.z;

    // loader: thread -> row (tid>>2), two 16B segs at (tid&3)*2
    int lrow = tid >> 2;
    int lseg = (tid & 3) * 2;
    int p = m0 + lrow;
    int bb = p >> 10, pix = p & 1023;
    int y = pix >> 5, x = pix & 31;
    long arow_base = (long)bb * a_bstride + (long)z * a_zstride;

    auto load_chunk = [&](int c, int st) {
        int koff = (c & 3) * 64;
        bool v = true;
        long arow;
        if (NTAP == 9) {
            int tap = c >> 2;
            int ky = tap/3 - 1, kx = tap%3 - 1;
            int yy = y + ky, xx = x + kx;
            v = ((unsigned)yy < 32u) && ((unsigned)xx < 32u);
            arow = arow_base + ((yy<<5) + xx);
        } else {
            arow = arow_base + pix;
        }
        const __half* asrc = v ? (A + arow*256 + koff + lseg*8) : A;
        uint32_t ab = sb + st*STAGE + lrow*ROWB + lseg*16;
        cp16(ab,      asrc,     v);
        cp16(ab + 16, asrc + 8, v);
        const __half* bsrc = Bw + (long)(n0 + lrow)*(NTAP*256) + c*64 + lseg*8;
        uint32_t bbs = sb + st*STAGE + STAGE_A + lrow*ROWB + lseg*16;
        cp16(bbs,      bsrc,     true);
        cp16(bbs + 16, bsrc + 8, true);
        CP_COMMIT();
    };

    int w = tid >> 5, l = tid & 31;
    int m_off = (w >> 2) * 32;
    int n_off = (w & 3) * 32;
    int lr = l & 15, lh = (l >> 4) << 4;

    float acc[2][4][4];
    #pragma unroll
    for (int i=0;i<2;i++)
        #pragma unroll
        for (int j=0;j<4;j++)
            #pragma unroll
            for (int q=0;q<4;q++) acc[i][j][q]=0.f;

    load_chunk(0, 0);
    if (NCHUNK > 1) load_chunk(1, 1); else CP_COMMIT();
    if (NCHUNK > 2) load_chunk(2, 2); else CP_COMMIT();

    for (int c = 0; c < NCHUNK; c++) {
        int st = c & (NSTAGE-1);
        if (c + 3 < NCHUNK) load_chunk(c + 3, (c + 3) & (NSTAGE-1));
        else CP_COMMIT();
        CP_WAIT3();
        __syncthreads();

        uint32_t a_st = sb + st*STAGE;
        uint32_t b_st = a_st + STAGE_A;
        #pragma unroll
        for (int ks = 0; ks < 4; ks++) {
            uint32_t af[2][4], bf[2][4];
            #pragma unroll
            for (int mt = 0; mt < 2; mt++)
                ldm_x4(af[mt], a_st + (m_off + mt*16 + lr)*ROWB + ks*32 + lh);
            #pragma unroll
            for (int nt = 0; nt < 2; nt++)
                ldm_x4(bf[nt], b_st + (n_off + nt*16 + lr)*ROWB + ks*32 + lh);
            #pragma unroll
            for (int mt = 0; mt < 2; mt++) {
                #pragma unroll
                for (int n8 = 0; n8 < 4; n8++) {
                    int nt = n8 >> 1, hi = n8 & 1;
                    mma16816(acc[mt][n8], af[mt], bf[nt][hi], bf[nt][2+hi]);
                }
            }
        }
        __syncthreads();
    }

    #pragma unroll
    for (int mt = 0; mt < 2; mt++) {
        int r0 = m0 + m_off + mt*16 + (l >> 2);
        #pragma unroll
        for (int n8 = 0; n8 < 4; n8++) {
            int cc = n0 + n_off + n8*8 + (l & 3)*2;
            float d0 = acc[mt][n8][0], d1 = acc[mt][n8][1];
            float d2 = acc[mt][n8][2], d3 = acc[mt][n8][3];
            if (EPI == 2) {
                float v0 = d0 + aux[(long)r0*128 + cc];
                float v1 = d1 + aux[(long)r0*128 + cc + 1];
                float v2 = d2 + aux[(long)(r0+8)*128 + cc];
                float v3 = d3 + aux[(long)(r0+8)*128 + cc + 1];
                __half h0,l0_,h1,l1_,h2,l2_,h3,l3_;
                split_h(v0,h0,l0_); split_h(v1,h1,l1_);
                split_h(v2,h2,l2_); split_h(v3,h3,l3_);
                outh[(long)r0*256 + cc]           = h0;
                outh[(long)r0*256 + cc + 1]       = h1;
                outh[(long)r0*256 + 128 + cc]     = l0_;
                outh[(long)r0*256 + 128 + cc + 1] = l1_;
                outh[(long)(r0+8)*256 + cc]           = h2;
                outh[(long)(r0+8)*256 + cc + 1]       = h3;
                outh[(long)(r0+8)*256 + 128 + cc]     = l2_;
                outh[(long)(r0+8)*256 + 128 + cc + 1] = l3_;
            } else {
                float* p0 = Out + ((long)z*o_zstride + r0    )*ldo + cc;
                float* p1 = Out + ((long)z*o_zstride + r0 + 8)*ldo + cc;
                if (EPI == 1) { d0 += p0[0]; d1 += p0[1]; d2 += p1[0]; d3 += p1[1]; }
                p0[0] = d0; p0[1] = d1;
                p1[0] = d2; p1[1] = d3;
            }
        }
    }
}

// -------------------- LSTM gates + output + h split --------------------
__global__ void gates_kernel(const float* __restrict__ cc,
                             float* __restrict__ cbuf,
                             __half* __restrict__ hp,
                             float* __restrict__ out, int s) {
    int idx = blockIdx.x*blockDim.x + threadIdx.x;
    if (idx >= Pn*En) return;
    int p = idx >> 7, e = idx & 127;
    const float* row = cc + (long)p*OC;
    float ci = row[e], cf = row[128+e], co = row[256+e], cg = row[384+e];
    float si = 1.f/(1.f+__expf(-ci));
    float sf = 1.f/(1.f+__expf(-cf));
    float so = 1.f/(1.f+__expf(-co));
    float c_prev = cbuf[idx];
    float c_next = sf*c_prev + si*tanhf(cg);
    float h_next = so*tanhf(c_next);
    cbuf[idx] = c_next;
    __half hi, lo;
    split_h(h_next, hi, lo);
    hp[(long)p*256 + e]       = hi;
    hp[(long)p*256 + 128 + e] = lo;
    int b = p >> 10, pix = p & 1023;
    out[((long)(b*16+s)*1024 + pix)*128 + e] = h_next;
}

// -------------------- launch --------------------
extern "C" void kernel_launch(void* const* d_in, const int* in_sizes, int n_in,
                              void* d_out, int out_size) {
    const float* inputs  = (const float*)d_in[0];
    const float* W_proj  = (const float*)d_in[1];
    const float* ln_g    = (const float*)d_in[2];
    const float* ln_b    = (const float*)d_in[3];
    const float* W_in    = (const float*)d_in[4];
    const float* W_out   = (const float*)d_in[5];
    const float* conv_k  = (const float*)d_in[6];
    float* out = (float*)d_out;

    float *qkv, *ccx, *cb;
    __half *xs2, *ao, *xp, *hp, *bx, *bh, *bqkv, *bout;
    cudaGetSymbolAddress((void**)&qkv, g_qkv);
    cudaGetSymbolAddress((void**)&ccx, g_ccx);
    cudaGetSymbolAddress((void**)&cb,  g_c);
    cudaGetSymbolAddress((void**)&xs2, g_xs2);
    cudaGetSymbolAddress((void**)&ao,  g_ao);
    cudaGetSymbolAddress((void**)&xp,  g_xp);
    cudaGetSymbolAddress((void**)&hp,  g_hp);
    cudaGetSymbolAddress((void**)&bx,  g_bx);
    cudaGetSymbolAddress((void**)&bh,  g_bh);
    cudaGetSymbolAddress((void**)&bqkv, g_bqkv);
    cudaGetSymbolAddress((void**)&bout, g_bout);

    cudaFuncSetAttribute(gemm_mma<1,0>, cudaFuncAttributeMaxDynamicSharedMemorySize, GEMM_SMEM);
    cudaFuncSetAttribute(gemm_mma<1,2>, cudaFuncAttributeMaxDynamicSharedMemorySize, GEMM_SMEM);
    cudaFuncSetAttribute(gemm_mma<9,0>, cudaFuncAttributeMaxDynamicSharedMemorySize, GEMM_SMEM);
    cudaFuncSetAttribute(gemm_mma<9,1>, cudaFuncAttributeMaxDynamicSharedMemorySize, GEMM_SMEM);

    zero_kernel<<<(Pn*En+255)/256, 256>>>(cb, Pn*En);
    reorder_conv<<<(int)(((long)OC*9*256 + 255)/256), 256>>>(conv_k, bx, bh);
    reorder_win<<<(384*256+255)/256, 256>>>(W_in, bqkv);
    reorder_wout<<<(128*256+255)/256, 256>>>(W_out, bout);

    projln_kernel<<<TOK/16, 128>>>(inputs, W_proj, ln_g, ln_b, xs2);

    // qkv = xln @ W_in  (M=131072, N=384, K'=256)
    gemm_mma<1,0><<<dim3(TOK/128, 3, 1), 512, GEMM_SMEM>>>(
        xs2, bqkv, qkv, 384, nullptr, nullptr, 1024L, 0L, 0L);

    attn_core<<<Pn, 128>>>(qkv, ao);

    // xres = ao @ W_out + inputs -> split fp16 xp
    gemm_mma<1,2><<<dim3(TOK/128, 1, 1), 512, GEMM_SMEM>>>(
        ao, bout, nullptr, 0, inputs, xp, 1024L, 0L, 0L);

    // batch-parallel conv_x over all 16 steps
    gemm_mma<9,0><<<dim3(Pn/128, 4, Sn), 512, GEMM_SMEM>>>(
        xp, bx, ccx, OC, nullptr, nullptr, 16384L, 1024L, 8192L);

    // sequential ConvLSTM
    for (int s = 0; s < Sn; s++) {
        if (s > 0) {
            gemm_mma<9,1><<<dim3(Pn/128, 4, 1), 512, GEMM_SMEM>>>(
                hp, bh, ccx + (long)s*Pn*OC, OC, nullptr, nullptr, 1024L, 0L, 0L);
        }
        gates_kernel<<<(Pn*En+255)/256, 256>>>(ccx + (long)s*Pn*OC, cb, hp, out, s);
    }
}

// round 5
// speedup vs baseline: 3.6529x; 1.5796x over previous
#include <cuda_runtime.h>
#include <cuda_fp16.h>
#include <cstdint>

// Problem constants
#define Bn 8
#define Sn 16
#define En 128
#define TOK (Bn*Sn*32*32)      // 131072
#define Pn (Bn*32*32)          // 8192
#define OC 512

// -------- scratch (device globals) --------
__device__ float g_projf[(long)TOK*128];      // 64MB  proj pre-act
__device__ float g_qkv[(long)TOK*384];        // 192MB
__device__ float g_ccx[(long)TOK*OC];         // 256MB
__device__ float g_c[Pn*En];
__device__ __half g_xin2[(long)TOK*256];      // inputs split (2-term)
__device__ __half g_xs2[(long)TOK*256];       // LN out split (2-term)
__device__ __half g_ao[(long)TOK*256];        // attn out split (2-term)
__device__ __half g_xp[(long)TOK*128];        // residual out (1-term, conv_x A)
__device__ __half g_hp[Pn*128];               // h (1-term, conv_h A)
__device__ __half g_bx[(long)OC*1152];        // conv weights x-half (1-term)
__device__ __half g_bh[(long)OC*1152];        // conv weights h-half (1-term)
__device__ __half g_bproj[128*256];
__device__ __half g_bqkv[384*256];
__device__ __half g_bout[128*256];

// ==================== helpers ====================
__device__ __forceinline__ uint32_t smem_u32(const void* p) {
    uint32_t a;
    asm("{ .reg .u64 t; cvta.to.shared.u64 t, %1; cvt.u32.u64 %0, t; }" : "=r"(a) : "l"(p));
    return a;
}
__device__ __forceinline__ void cp16(uint32_t dst, const void* src, bool pred) {
    asm volatile("cp.async.cg.shared.global [%0], [%1], 16, %2;"
        :: "r"(dst), "l"(src), "r"(pred ? 16u : 0u));
}
#define CP_COMMIT() asm volatile("cp.async.commit_group;" ::: "memory")
#define CP_WAIT3()  asm volatile("cp.async.wait_group 3;" ::: "memory")

__device__ __forceinline__ void ldm_x4(uint32_t* r, uint32_t addr) {
    asm volatile("ldmatrix.sync.aligned.m8n8.x4.shared.b16 {%0,%1,%2,%3}, [%4];"
        : "=r"(r[0]), "=r"(r[1]), "=r"(r[2]), "=r"(r[3]) : "r"(addr));
}
__device__ __forceinline__ void mma16816(float* d, const uint32_t* a, uint32_t b0, uint32_t b1) {
    asm volatile("mma.sync.aligned.m16n8k16.row.col.f32.f16.f16.f32 "
        "{%0,%1,%2,%3}, {%4,%5,%6,%7}, {%8,%9}, {%0,%1,%2,%3};"
        : "+f"(d[0]), "+f"(d[1]), "+f"(d[2]), "+f"(d[3])
        : "r"(a[0]), "r"(a[1]), "r"(a[2]), "r"(a[3]), "r"(b0), "r"(b1));
}
__device__ __forceinline__ void split_h(float x, __half& hi, __half& lo) {
    hi = __float2half(x);
    lo = __float2half(x - __half2float(hi));
}

// -------------------- small kernels --------------------
__global__ void zero_kernel(float* p, int n) {
    int i = blockIdx.x*blockDim.x + threadIdx.x;
    if (i < n) p[i] = 0.f;
}
// inputs f32 -> 2-term fp16 [hi|lo] rows of 256
__global__ void split_in(const float* __restrict__ inp, __half* __restrict__ x2) {
    long idx = (long)blockIdx.x*blockDim.x + threadIdx.x;
    if (idx >= (long)TOK*128) return;
    long row = idx >> 7; int e = idx & 127;
    __half hi, lo;
    split_h(inp[idx], hi, lo);
    x2[row*256 + e]       = hi;
    x2[row*256 + 128 + e] = lo;
}
// conv weights: (512,256,3,3) -> B[oc][tap*128+ic] 1-term fp16
__global__ void reorder_conv(const float* __restrict__ ck,
                             __half* __restrict__ bx, __half* __restrict__ bh) {
    long idx = (long)blockIdx.x*blockDim.x + threadIdx.x;
    if (idx >= (long)OC*1152) return;
    int oc = idx / 1152, k = idx % 1152;
    int tap = k >> 7, ic = k & 127;
    int ky = tap / 3, kx = tap % 3;
    bx[idx] = __float2half(ck[(((long)oc*256 + ic      )*3 + ky)*3 + kx]);
    bh[idx] = __float2half(ck[(((long)oc*256 + 128 + ic)*3 + ky)*3 + kx]);
}
// dense weight (K=128 rows, N cols) -> B[n][256] = [w|w]
template<int N>
__global__ void reorder_w2(const float* __restrict__ w, __half* __restrict__ b) {
    int idx = blockIdx.x*blockDim.x + threadIdx.x;
    if (idx >= N*128) return;
    int n = idx >> 7, k = idx & 127;
    __half v = __float2half(w[k*N + n]);
    b[n*256 + k]       = v;
    b[n*256 + 128 + k] = v;
}

// -------------------- silu + LN (reads proj result) --------------------
__global__ __launch_bounds__(128)
void siluln_kernel(const float* __restrict__ projf,
                   const float* __restrict__ gamma, const float* __restrict__ beta,
                   __half* __restrict__ xs2) {
    __shared__ float xs[16][128];
    __shared__ float mu_s[16], rs_s[16];
    long tok0 = (long)blockIdx.x * 16;
    int j = threadIdx.x;
    #pragma unroll
    for (int t=0;t<16;t++) {
        float v = projf[(tok0+t)*128 + j];
        xs[t][j] = v / (1.0f + __expf(-v));
    }
    __syncthreads();
    int warp = j >> 5, lane = j & 31;
    for (int t = warp*4; t < warp*4+4; t++) {
        float a0 = xs[t][lane], a1 = xs[t][lane+32], a2 = xs[t][lane+64], a3 = xs[t][lane+96];
        float s = a0+a1+a2+a3;
        float q = a0*a0+a1*a1+a2*a2+a3*a3;
        #pragma unroll
        for (int off=16; off; off>>=1) {
            s += __shfl_xor_sync(0xffffffff, s, off);
            q += __shfl_xor_sync(0xffffffff, q, off);
        }
        if (lane==0) {
            float mu = s * (1.0f/128.0f);
            float var = q * (1.0f/128.0f) - mu*mu;
            mu_s[t] = mu;
            rs_s[t] = rsqrtf(var + 1e-5f);
        }
    }
    __syncthreads();
    float g = gamma[j], bt = beta[j];
    #pragma unroll
    for (int t=0;t<16;t++) {
        float v = (xs[t][j]-mu_s[t])*rs_s[t]*g + bt;
        __half hi, lo;
        split_h(v, hi, lo);
        xs2[(tok0+t)*256 + j]       = hi;
        xs2[(tok0+t)*256 + 128 + j] = lo;
    }
}

// -------------------- attention core (softmax + AV) --------------------
__global__ __launch_bounds__(128)
void attn_core(const float* __restrict__ qkv, __half* __restrict__ ao) {
    __shared__ float qs[16][384];
    int bid = blockIdx.x;
    int b = bid >> 10, hw = bid & 1023;
    int tid = threadIdx.x;
    for (int idx = tid; idx < 16*96; idx += 128) {
        int t = idx / 96, f = idx % 96;
        ((float4*)qs[t])[f] =
            ((const float4*)(qkv + ((long)(b*16+t)*1024 + hw)*384))[f];
    }
    __syncthreads();
    int i = tid >> 4, srow = tid & 15;
    float qd[16];
    #pragma unroll
    for (int d=0; d<16; d++) qd[d] = qs[srow][i*48+d];
    float sc[16];
    float mx = -1e30f;
    #pragma unroll
    for (int l=0;l<16;l++) {
        float sv = 0.f;
        #pragma unroll
        for (int d=0;d<16;d++) sv += qd[d]*qs[l][i*48+16+d];
        sv = sv*0.25f + (l<=srow ? 1.0f : -1000.0f);
        sc[l]=sv; mx = fmaxf(mx, sv);
    }
    float sum=0.f;
    #pragma unroll
    for (int l=0;l<16;l++){ sc[l]=__expf(sc[l]-mx); sum+=sc[l]; }
    float inv = 1.0f/sum;
    float o[16];
    #pragma unroll
    for (int d=0;d<16;d++) o[d]=0.f;
    #pragma unroll
    for (int l=0;l<16;l++) {
        float wl = sc[l]*inv;
        #pragma unroll
        for (int d=0;d<16;d++) o[d] += wl*qs[l][i*48+32+d];
    }
    long t = (long)(b*16+srow)*1024 + hw;
    #pragma unroll
    for (int d=0;d<16;d++) {
        __half hi, lo;
        split_h(o[d], hi, lo);
        ao[t*256 + i*16 + d]       = hi;
        ao[t*256 + 128 + i*16 + d] = lo;
    }
}

// -------------------- universal warp-MMA fp16 GEMM / implicit conv --------------------
// CTA 128x128, 16 warps 32x32, chunks of 64, 4-stage cp.async.
// NTAP=1: dense GEMM, A rows 256 (2-term).  NTAP=9: conv gather, A rows 128 (1-term).
// EPI: 0 store f32, 1 accumulate f32, 2 = +residual -> fp16 hi only (128-wide rows).
#define ROWB 144
#define STAGE_A (128*ROWB)
#define STAGE   (2*STAGE_A)       // 36864
#define NSTAGE  4
#define GEMM_SMEM (NSTAGE*STAGE)  // 147456

template<int NTAP, int EPI>
__global__ __launch_bounds__(512, 1)
void gemm_mma(const __half* __restrict__ A, const __half* __restrict__ Bw,
              float* __restrict__ Out, int ldo,
              const float* __restrict__ aux, __half* __restrict__ outh,
              long a_bstride, long a_zstride, long o_zstride) {
    constexpr int ALEN   = (NTAP == 9) ? 128 : 256;
    constexpr int CPT    = ALEN / 64;          // chunks per tap
    constexpr int NCHUNK = NTAP * CPT;
    extern __shared__ char smem[];
    uint32_t sb = smem_u32(smem);

    int tid = threadIdx.x;
    int m0 = blockIdx.x * 128;
    int n0 = blockIdx.y * 128;
    int z  = blockIdx.z;

    int lrow = tid >> 2;
    int lseg = (tid & 3) * 2;
    int p = m0 + lrow;
    int bb = p >> 10, pix = p & 1023;
    int y = pix >> 5, x = pix & 31;
    long arow_base = (long)bb * a_bstride + (long)z * a_zstride;

    auto load_chunk = [&](int c, int st) {
        int koff = (c % CPT) * 64;
        bool v = true;
        long arow;
        if (NTAP == 9) {
            int tap = c / CPT;
            int ky = tap/3 - 1, kx = tap%3 - 1;
            int yy = y + ky, xx = x + kx;
            v = ((unsigned)yy < 32u) && ((unsigned)xx < 32u);
            arow = arow_base + ((yy<<5) + xx);
        } else {
            arow = arow_base + pix;
        }
        const __half* asrc = v ? (A + arow*ALEN + koff + lseg*8) : A;
        uint32_t ab = sb + st*STAGE + lrow*ROWB + lseg*16;
        cp16(ab,      asrc,     v);
        cp16(ab + 16, asrc + 8, v);
        const __half* bsrc = Bw + (long)(n0 + lrow)*(NTAP*ALEN) + c*64 + lseg*8;
        uint32_t bbs = sb + st*STAGE + STAGE_A + lrow*ROWB + lseg*16;
        cp16(bbs,      bsrc,     true);
        cp16(bbs + 16, bsrc + 8, true);
        CP_COMMIT();
    };

    int w = tid >> 5, l = tid & 31;
    int m_off = (w >> 2) * 32;
    int n_off = (w & 3) * 32;
    int lr = l & 15, lh = (l >> 4) << 4;

    float acc[2][4][4];
    #pragma unroll
    for (int i=0;i<2;i++)
        #pragma unroll
        for (int j=0;j<4;j++)
            #pragma unroll
            for (int q=0;q<4;q++) acc[i][j][q]=0.f;

    load_chunk(0, 0);
    if (NCHUNK > 1) load_chunk(1, 1); else CP_COMMIT();
    if (NCHUNK > 2) load_chunk(2, 2); else CP_COMMIT();

    for (int c = 0; c < NCHUNK; c++) {
        int st = c & (NSTAGE-1);
        if (c + 3 < NCHUNK) load_chunk(c + 3, (c + 3) & (NSTAGE-1));
        else CP_COMMIT();
        CP_WAIT3();
        __syncthreads();

        uint32_t a_st = sb + st*STAGE;
        uint32_t b_st = a_st + STAGE_A;
        #pragma unroll
        for (int ks = 0; ks < 4; ks++) {
            uint32_t af[2][4], bf[2][4];
            #pragma unroll
            for (int mt = 0; mt < 2; mt++)
                ldm_x4(af[mt], a_st + (m_off + mt*16 + lr)*ROWB + ks*32 + lh);
            #pragma unroll
            for (int nt = 0; nt < 2; nt++)
                ldm_x4(bf[nt], b_st + (n_off + nt*16 + lr)*ROWB + ks*32 + lh);
            #pragma unroll
            for (int mt = 0; mt < 2; mt++) {
                #pragma unroll
                for (int n8 = 0; n8 < 4; n8++) {
                    int nt = n8 >> 1, hi = n8 & 1;
                    mma16816(acc[mt][n8], af[mt], bf[nt][hi], bf[nt][2+hi]);
                }
            }
        }
        __syncthreads();
    }

    #pragma unroll
    for (int mt = 0; mt < 2; mt++) {
        int r0 = m0 + m_off + mt*16 + (l >> 2);
        #pragma unroll
        for (int n8 = 0; n8 < 4; n8++) {
            int cc = n0 + n_off + n8*8 + (l & 3)*2;
            float d0 = acc[mt][n8][0], d1 = acc[mt][n8][1];
            float d2 = acc[mt][n8][2], d3 = acc[mt][n8][3];
            if (EPI == 2) {
                float v0 = d0 + aux[(long)r0*128 + cc];
                float v1 = d1 + aux[(long)r0*128 + cc + 1];
                float v2 = d2 + aux[(long)(r0+8)*128 + cc];
                float v3 = d3 + aux[(long)(r0+8)*128 + cc + 1];
                outh[(long)r0*128 + cc]         = __float2half(v0);
                outh[(long)r0*128 + cc + 1]     = __float2half(v1);
                outh[(long)(r0+8)*128 + cc]     = __float2half(v2);
                outh[(long)(r0+8)*128 + cc + 1] = __float2half(v3);
            } else {
                float* p0 = Out + ((long)z*o_zstride + r0    )*ldo + cc;
                float* p1 = Out + ((long)z*o_zstride + r0 + 8)*ldo + cc;
                if (EPI == 1) { d0 += p0[0]; d1 += p0[1]; d2 += p1[0]; d3 += p1[1]; }
                p0[0] = d0; p0[1] = d1;
                p1[0] = d2; p1[1] = d3;
            }
        }
    }
}

// -------------------- LSTM gates + output + h (1-term) --------------------
__global__ void gates_kernel(const float* __restrict__ cc,
                             float* __restrict__ cbuf,
                             __half* __restrict__ hp,
                             float* __restrict__ out, int s) {
    int idx = blockIdx.x*blockDim.x + threadIdx.x;
    if (idx >= Pn*En) return;
    int p = idx >> 7, e = idx & 127;
    const float* row = cc + (long)p*OC;
    float ci = row[e], cf = row[128+e], co = row[256+e], cg = row[384+e];
    float si = 1.f/(1.f+__expf(-ci));
    float sf = 1.f/(1.f+__expf(-cf));
    float so = 1.f/(1.f+__expf(-co));
    float c_prev = cbuf[idx];
    float c_next = sf*c_prev + si*tanhf(cg);
    float h_next = so*tanhf(c_next);
    cbuf[idx] = c_next;
    hp[(long)p*128 + e] = __float2half(h_next);
    int b = p >> 10, pix = p & 1023;
    out[((long)(b*16+s)*1024 + pix)*128 + e] = h_next;
}

// -------------------- launch --------------------
extern "C" void kernel_launch(void* const* d_in, const int* in_sizes, int n_in,
                              void* d_out, int out_size) {
    const float* inputs  = (const float*)d_in[0];
    const float* W_proj  = (const float*)d_in[1];
    const float* ln_g    = (const float*)d_in[2];
    const float* ln_b    = (const float*)d_in[3];
    const float* W_in    = (const float*)d_in[4];
    const float* W_out   = (const float*)d_in[5];
    const float* conv_k  = (const float*)d_in[6];
    float* out = (float*)d_out;

    float *projf, *qkv, *ccx, *cb;
    __half *xin2, *xs2, *ao, *xp, *hp, *bx, *bh, *bproj, *bqkv, *bout;
    cudaGetSymbolAddress((void**)&projf, g_projf);
    cudaGetSymbolAddress((void**)&qkv, g_qkv);
    cudaGetSymbolAddress((void**)&ccx, g_ccx);
    cudaGetSymbolAddress((void**)&cb,  g_c);
    cudaGetSymbolAddress((void**)&xin2, g_xin2);
    cudaGetSymbolAddress((void**)&xs2, g_xs2);
    cudaGetSymbolAddress((void**)&ao,  g_ao);
    cudaGetSymbolAddress((void**)&xp,  g_xp);
    cudaGetSymbolAddress((void**)&hp,  g_hp);
    cudaGetSymbolAddress((void**)&bx,  g_bx);
    cudaGetSymbolAddress((void**)&bh,  g_bh);
    cudaGetSymbolAddress((void**)&bproj, g_bproj);
    cudaGetSymbolAddress((void**)&bqkv, g_bqkv);
    cudaGetSymbolAddress((void**)&bout, g_bout);

    cudaFuncSetAttribute(gemm_mma<1,0>, cudaFuncAttributeMaxDynamicSharedMemorySize, GEMM_SMEM);
    cudaFuncSetAttribute(gemm_mma<1,2>, cudaFuncAttributeMaxDynamicSharedMemorySize, GEMM_SMEM);
    cudaFuncSetAttribute(gemm_mma<9,0>, cudaFuncAttributeMaxDynamicSharedMemorySize, GEMM_SMEM);
    cudaFuncSetAttribute(gemm_mma<9,1>, cudaFuncAttributeMaxDynamicSharedMemorySize, GEMM_SMEM);

    zero_kernel<<<(Pn*En+255)/256, 256>>>(cb, Pn*En);
    reorder_conv<<<(int)(((long)OC*1152 + 255)/256), 256>>>(conv_k, bx, bh);
    reorder_w2<128><<<(128*128+255)/256, 256>>>(W_proj, bproj);
    reorder_w2<384><<<(384*128+255)/256, 256>>>(W_in, bqkv);
    reorder_w2<128><<<(128*128+255)/256, 256>>>(W_out, bout);
    split_in<<<(int)(((long)TOK*128+255)/256), 256>>>(inputs, xin2);

    // proj = inputs @ W_proj (2-term)
    gemm_mma<1,0><<<dim3(TOK/128, 1, 1), 512, GEMM_SMEM>>>(
        xin2, bproj, projf, 128, nullptr, nullptr, 1024L, 0L, 0L);

    siluln_kernel<<<TOK/16, 128>>>(projf, ln_g, ln_b, xs2);

    // qkv = xln @ W_in (2-term)
    gemm_mma<1,0><<<dim3(TOK/128, 3, 1), 512, GEMM_SMEM>>>(
        xs2, bqkv, qkv, 384, nullptr, nullptr, 1024L, 0L, 0L);

    attn_core<<<Pn, 128>>>(qkv, ao);

    // xres = ao @ W_out + inputs -> 1-term fp16 xp
    gemm_mma<1,2><<<dim3(TOK/128, 1, 1), 512, GEMM_SMEM>>>(
        ao, bout, nullptr, 0, inputs, xp, 1024L, 0L, 0L);

    // batch-parallel conv_x over all 16 steps (1-term)
    gemm_mma<9,0><<<dim3(Pn/128, 4, Sn), 512, GEMM_SMEM>>>(
        xp, bx, ccx, OC, nullptr, nullptr, 16384L, 1024L, 8192L);

    // sequential ConvLSTM
    for (int s = 0; s < Sn; s++) {
        if (s > 0) {
            gemm_mma<9,1><<<dim3(Pn/128, 4, 1), 512, GEMM_SMEM>>>(
                hp, bh, ccx + (long)s*Pn*OC, OC, nullptr, nullptr, 1024L, 0L, 0L);
        }
        gates_kernel<<<(Pn*En+255)/256, 256>>>(ccx + (long)s*Pn*OC, cb, hp, out, s);
    }
}